// round 9
// baseline (speedup 1.0000x reference)
#include <cuda_runtime.h>
#include <stdint.h>
#include <math.h>

static constexpr int BATCH  = 16;
static constexpr int C      = 128;
static constexpr int N      = 16384;
static constexpr int SPLITK = 16;
static constexpr int CHUNK  = N / SPLITK;    // 1024
static constexpr int NTILES = N / 128;       // 128
static constexpr size_t OUT_ELEMS = (size_t)BATCH * C * N;
static constexpr int LDS_ = 136;             // padded smem stride (words)

// ---------------- scratch (static device globals; no allocations) ----------
__device__ float g_kg  [(size_t)BATCH * C * N];          // tf32 bit patterns
__device__ float g_v   [(size_t)BATCH * C * N];          // tf32 bit patterns
__device__ float g_part[(size_t)BATCH * SPLITK * C * C];
__device__ float g_fsum[(size_t)BATCH * NTILES * C];     // [b][tile][c]
__device__ float g_E   [(size_t)BATCH * C * C];
__device__ float g_F   [(size_t)BATCH * C * C];
__device__ float g_fb  [(size_t)BATCH * C];

__device__ __forceinline__ float sigmoidf_(float v) { return 1.0f / (1.0f + __expf(-v)); }

__device__ __forceinline__ uint32_t f2tf(float f) {
    uint32_t u; asm("cvt.rna.tf32.f32 %0, %1;" : "=r"(u) : "f"(f)); return u;
}

__device__ __forceinline__ void mma_tf32(float c[4],
    uint32_t a0, uint32_t a1, uint32_t a2, uint32_t a3, uint32_t b0, uint32_t b1)
{
    asm volatile(
        "mma.sync.aligned.m16n8k8.row.col.f32.tf32.tf32.f32 "
        "{%0,%1,%2,%3}, {%4,%5,%6,%7}, {%8,%9}, {%0,%1,%2,%3};\n"
        : "+f"(c[0]), "+f"(c[1]), "+f"(c[2]), "+f"(c[3])
        : "r"(a0), "r"(a1), "r"(a2), "r"(a3), "r"(b0), "r"(b1));
}

// ---- 8-deep slab loaders (256 threads cover 8x128) -------------------------
// transpose STS: thread owns m = tid>>1, koff = (tid&1)*4
__device__ __forceinline__ void stsT(uint32_t (*S)[LDS_], float4 r, int tid) {
    const int m = tid >> 1, ko = (tid & 1) << 2;
    S[ko + 0][m] = f2tf(r.x); S[ko + 1][m] = f2tf(r.y);
    S[ko + 2][m] = f2tf(r.z); S[ko + 3][m] = f2tf(r.w);
}
__device__ __forceinline__ void stsT_raw(uint32_t (*S)[LDS_], uint4 r, int tid) {
    const int m = tid >> 1, ko = (tid & 1) << 2;
    S[ko + 0][m] = r.x; S[ko + 1][m] = r.y;
    S[ko + 2][m] = r.z; S[ko + 3][m] = r.w;
}
// direct STS: thread owns kb = tid>>5, nb = (tid&31)*4
__device__ __forceinline__ void stsD(uint32_t (*S)[LDS_], float4 r, int tid) {
    const int kb = tid >> 5, nb = (tid & 31) << 2;
    *(uint4*)&S[kb][nb] = make_uint4(f2tf(r.x), f2tf(r.y), f2tf(r.z), f2tf(r.w));
}

// One 8-deep K-slab. Warp tile 64x32 (4 mfrag x 4 nfrag).
// Frag maps (m16n8k8 tf32): a0(g,tig) a1(g+8,tig) a2(g,tig+4) a3(g+8,tig+4);
// b0(tig,g) b1(tig+4,g); c0(g,2tig) c1(g,2tig+1) c2(g+8,2tig) c3(g+8,2tig+1).
__device__ __forceinline__ void compute_slab8(const uint32_t (*As)[LDS_], const uint32_t (*Bs)[LDS_],
                                              float acc[4][4][4], int mrow, int ncol, int g, int tig)
{
    uint32_t a[4][4], b[4][2];
#pragma unroll
    for (int mf = 0; mf < 4; mf++) {
        const int m = mrow + mf * 16 + g;
        a[mf][0] = As[tig][m];     a[mf][1] = As[tig][m + 8];
        a[mf][2] = As[tig + 4][m]; a[mf][3] = As[tig + 4][m + 8];
    }
#pragma unroll
    for (int nf = 0; nf < 4; nf++) {
        const int n = ncol + nf * 8 + g;
        b[nf][0] = Bs[tig][n]; b[nf][1] = Bs[tig + 4][n];
    }
#pragma unroll
    for (int mf = 0; mf < 4; mf++)
#pragma unroll
        for (int nf = 0; nf < 4; nf++)
            mma_tf32(acc[mf][nf], a[mf][0], a[mf][1], a[mf][2], a[mf][3],
                     b[nf][0], b[nf][1]);
}

// ---------------------------------------------------------------------------
// Kernel 1: fused projections, software-pipelined.
// ---------------------------------------------------------------------------
__global__ void __launch_bounds__(256, 2)
proj_tc(const float* __restrict__ x,
        const float* __restrict__ Wk, const float* __restrict__ bk,
        const float* __restrict__ Wv, const float* __restrict__ bv,
        const float* __restrict__ Wg, const float* __restrict__ bg)
{
    __shared__ uint32_t As[2][8][LDS_];
    __shared__ uint32_t Bs[2][8][LDS_];
    __shared__ float red[64][4];

    const int idx   = blockIdx.x;
    const int type  = idx >> 1;
    const int cbase = (idx & 1) * 64;
    const int n0    = blockIdx.y << 7;
    const int b     = blockIdx.z;

    const float *W1, *W2, *b1, *b2;
    if (type == 0) { W1 = Wk; b1 = bk; W2 = Wg + C * C; b2 = bg + C; }
    else           { W1 = Wv; b1 = bv; W2 = Wg;         b2 = bg;     }

    const int tid = threadIdx.x, lane = tid & 31, warp = tid >> 5;
    const int g = lane >> 2, tig = lane & 3;
    const int warpM = warp & 1, warpN = warp >> 1;
    const int mrow = warpM * 64, ncol = warpN * 32;

    // A rows: group = m>>4 holds 8 channels; wi<8 -> W1 row, wi>=8 -> W2 row
    const int am = tid >> 1;
    const int agrp = am >> 4, awi = am & 15;
    const int ach = cbase + agrp * 8 + (awi & 7);
    const float* aptr = ((awi < 8) ? W1 : W2) + (size_t)ach * C + ((tid & 1) << 2);
    const float* xb = x + (size_t)b * C * N;
    const float* bptr = xb + (size_t)(tid >> 5) * N + n0 + ((tid & 31) << 2);

    float4 ra = *(const float4*)aptr;
    float4 rb = *(const float4*)bptr;
    stsT(As[0], ra, tid); stsD(Bs[0], rb, tid);
    __syncthreads();

    float acc[4][4][4] = {};
#pragma unroll 1
    for (int s = 0; s < 16; s++) {
        const int cur = s & 1;
        if (s < 15) {
            ra = *(const float4*)(aptr + (s + 1) * 8);
            rb = *(const float4*)(bptr + (size_t)(s + 1) * 8 * N);
        }
        compute_slab8(As[cur], Bs[cur], acc, mrow, ncol, g, tig);
        if (s < 15) {
            stsT(As[cur ^ 1], ra, tid); stsD(Bs[cur ^ 1], rb, tid);
            __syncthreads();
        }
    }

    if (type == 0) {
#pragma unroll
        for (int mf = 0; mf < 4; mf++) {
            const int ch = cbase + (warpM * 4 + mf) * 8 + g;
            const float bb1 = b1[ch], bb2 = b2[ch];
            float* dst = g_kg + ((size_t)b * C + ch) * N + n0 + ncol + 2 * tig;
#pragma unroll
            for (int nf = 0; nf < 4; nf++) {
                float o0 = (acc[mf][nf][0] + bb1) * sigmoidf_(acc[mf][nf][2] + bb2);
                float o1 = (acc[mf][nf][1] + bb1) * sigmoidf_(acc[mf][nf][3] + bb2);
                // pre-convert to tf32 (RNA is idempotent -> numerics identical)
                *(float2*)(dst + nf * 8) = make_float2(__uint_as_float(f2tf(o0)),
                                                       __uint_as_float(f2tf(o1)));
            }
        }
    } else {
#pragma unroll
        for (int mf = 0; mf < 4; mf++) {
            const int ch = cbase + (warpM * 4 + mf) * 8 + g;
            const float bb1 = b1[ch], bb2 = b2[ch];
            float* dv = g_v + ((size_t)b * C + ch) * N + n0 + ncol + 2 * tig;
            float s = 0.f;
#pragma unroll
            for (int nf = 0; nf < 4; nf++) {
                float o0 = acc[mf][nf][0] + bb1;
                float o1 = acc[mf][nf][1] + bb1;
                *(float2*)(dv + nf * 8) = make_float2(__uint_as_float(f2tf(o0)),
                                                      __uint_as_float(f2tf(o1)));
                s += sigmoidf_(acc[mf][nf][2] + bb2) + sigmoidf_(acc[mf][nf][3] + bb2);
            }
            s += __shfl_xor_sync(0xffffffffu, s, 1);
            s += __shfl_xor_sync(0xffffffffu, s, 2);
            if (tig == 0) red[warpM * 32 + mf * 8 + g][warpN] = s;
        }
        __syncthreads();
        if (tid < 64) {
            float s = red[tid][0] + red[tid][1] + red[tid][2] + red[tid][3];
            g_fsum[((size_t)b * NTILES + blockIdx.y) * C + cbase + tid] = s;
        }
    }
}

// ---------------------------------------------------------------------------
// Kernel 2: knowledge partials (NT GEMM), pipelined, raw tf32 loads (no cvt).
// ---------------------------------------------------------------------------
__global__ void __launch_bounds__(256, 2)
know_tc()
{
    __shared__ uint32_t As[2][8][LDS_];
    __shared__ uint32_t Bs[2][8][LDS_];

    const int s = blockIdx.x, b = blockIdx.y;
    const int tid = threadIdx.x, lane = tid & 31, warp = tid >> 5;
    const int g = lane >> 2, tig = lane & 3;
    const int warpM = warp & 1, warpN = warp >> 1;
    const int mrow = warpM * 64, ncol = warpN * 32;

    const size_t base = ((size_t)b * C + (tid >> 1)) * N + (size_t)s * CHUNK + ((tid & 1) << 2);
    const float* aptr = g_kg + base;
    const float* bptr = g_v  + base;

    uint4 ra = *(const uint4*)aptr;
    uint4 rb = *(const uint4*)bptr;
    stsT_raw(As[0], ra, tid); stsT_raw(Bs[0], rb, tid);
    __syncthreads();

    float acc[4][4][4] = {};
#pragma unroll 1
    for (int ss = 0; ss < CHUNK / 8; ss++) {
        const int cur = ss & 1;
        if (ss < CHUNK / 8 - 1) {
            ra = *(const uint4*)(aptr + (ss + 1) * 8);
            rb = *(const uint4*)(bptr + (ss + 1) * 8);
        }
        compute_slab8(As[cur], Bs[cur], acc, mrow, ncol, g, tig);
        if (ss < CHUNK / 8 - 1) {
            stsT_raw(As[cur ^ 1], ra, tid); stsT_raw(Bs[cur ^ 1], rb, tid);
            __syncthreads();
        }
    }

    float* dst = g_part + ((size_t)b * SPLITK + s) * C * C;
#pragma unroll
    for (int mf = 0; mf < 4; mf++) {
        const int row = mrow + mf * 16 + g;
#pragma unroll
        for (int nf = 0; nf < 4; nf++) {
            const int col = ncol + nf * 8 + 2 * tig;
            *(float2*)(dst + (size_t)row * C + col)       = make_float2(acc[mf][nf][0], acc[mf][nf][1]);
            *(float2*)(dst + (size_t)(row + 8) * C + col) = make_float2(acc[mf][nf][2], acc[mf][nf][3]);
        }
    }
}

// ---------------------------------------------------------------------------
// Kernel 3 (fused tail): per batch block:
//   phase 1: fs = mean(sig(forget))
//   phase 2: M = fs*prev + sum(partials) -> d_out tail
//   phase 3: E = Wp * M^T -> g_E
//   phase 4: F = E * Wq -> g_F ; fb = E*bq + bp
// __syncthreads() provides block-scope global-memory visibility between phases.
// ---------------------------------------------------------------------------
__global__ void __launch_bounds__(256, 2)
tail_tc(const float* __restrict__ prev, const float* __restrict__ Wp,
        const float* __restrict__ Wq, const float* __restrict__ bq,
        const float* __restrict__ bp, float* __restrict__ dout)
{
    __shared__ uint32_t As[2][8][LDS_];
    __shared__ uint32_t Bs[2][8][LDS_];
    __shared__ float fs[128];

    const int b = blockIdx.x;
    const int tid = threadIdx.x, lane = tid & 31, warp = tid >> 5;
    const int g = lane >> 2, tig = lane & 3;
    const int warpM = warp & 1, warpN = warp >> 1;
    const int mrow = warpM * 64, ncol = warpN * 32;

    // phase 1
    if (tid < 128) {
        const float* p = g_fsum + (size_t)b * NTILES * C + tid;
        float sm = 0.f;
        for (int i = 0; i < NTILES; i++) sm += p[(size_t)i * C];
        fs[tid] = sm * (1.0f / (float)N);
    }
    __syncthreads();

    // phase 2
    float* M = dout + OUT_ELEMS + (size_t)b * C * C;
    for (int e = tid; e < C * C; e += 256) {
        const int c = e >> 7;
        float a = fs[c] * prev[(size_t)b * C * C + e];
#pragma unroll
        for (int s2 = 0; s2 < SPLITK; s2++)
            a += g_part[((size_t)b * SPLITK + s2) * C * C + e];
        M[e] = a;
    }
    __syncthreads();

    // phase 3: E = Wp * M^T   (As[k=d][o]=Wp[o][d], Bs[k=d][c]=M[c][d])
    {
        const int am = tid >> 1;
        const float* aptr = Wp + (size_t)am * C + ((tid & 1) << 2);
        const float* bptr = M  + (size_t)am * C + ((tid & 1) << 2);
        float4 ra = *(const float4*)aptr;
        float4 rb = *(const float4*)bptr;
        stsT(As[0], ra, tid); stsT(Bs[0], rb, tid);
        __syncthreads();
        float acc[4][4][4] = {};
#pragma unroll 1
        for (int s = 0; s < 16; s++) {
            const int cur = s & 1;
            if (s < 15) {
                ra = *(const float4*)(aptr + (s + 1) * 8);
                rb = *(const float4*)(bptr + (s + 1) * 8);
            }
            compute_slab8(As[cur], Bs[cur], acc, mrow, ncol, g, tig);
            if (s < 15) { stsT(As[cur ^ 1], ra, tid); stsT(Bs[cur ^ 1], rb, tid); __syncthreads(); }
        }
        float* dst = g_E + (size_t)b * C * C;
#pragma unroll
        for (int mf = 0; mf < 4; mf++) {
            const int row = mrow + mf * 16 + g;
#pragma unroll
            for (int nf = 0; nf < 4; nf++) {
                const int col = ncol + nf * 8 + 2 * tig;
                *(float2*)(dst + (size_t)row * C + col)       = make_float2(acc[mf][nf][0], acc[mf][nf][1]);
                *(float2*)(dst + (size_t)(row + 8) * C + col) = make_float2(acc[mf][nf][2], acc[mf][nf][3]);
            }
        }
    }
    __syncthreads();

    // phase 4: F = E * Wq  (As[k=c][o]=E[o][c], Bs[k=c][j]=Wq[c][j]); fb
    {
        const float* E = g_E + (size_t)b * C * C;
        const int am = tid >> 1;
        const float* aptr = E + (size_t)am * C + ((tid & 1) << 2);
        const float* bptr = Wq + (size_t)(tid >> 5) * C + ((tid & 31) << 2);
        float4 ra = *(const float4*)aptr;
        float4 rb = *(const float4*)bptr;
        stsT(As[0], ra, tid); stsD(Bs[0], rb, tid);
        __syncthreads();
        float acc[4][4][4] = {};
#pragma unroll 1
        for (int s = 0; s < 16; s++) {
            const int cur = s & 1;
            if (s < 15) {
                ra = *(const float4*)(aptr + (s + 1) * 8);
                rb = *(const float4*)(bptr + (size_t)(s + 1) * 8 * C);
            }
            compute_slab8(As[cur], Bs[cur], acc, mrow, ncol, g, tig);
            if (s < 15) { stsT(As[cur ^ 1], ra, tid); stsD(Bs[cur ^ 1], rb, tid); __syncthreads(); }
        }
        float* dst = g_F + (size_t)b * C * C;
#pragma unroll
        for (int mf = 0; mf < 4; mf++) {
            const int row = mrow + mf * 16 + g;
#pragma unroll
            for (int nf = 0; nf < 4; nf++) {
                const int col = ncol + nf * 8 + 2 * tig;
                *(float2*)(dst + (size_t)row * C + col)       = make_float2(acc[mf][nf][0], acc[mf][nf][1]);
                *(float2*)(dst + (size_t)(row + 8) * C + col) = make_float2(acc[mf][nf][2], acc[mf][nf][3]);
            }
        }
        __syncthreads();
        if (tid < 128) {
            float sm = bp[tid];
            const float* er = E + (size_t)tid * C;
            for (int c = 0; c < C; c++) sm = fmaf(er[c], bq[c], sm);
            g_fb[(size_t)b * C + tid] = sm;
        }
    }
}

// ---------------------------------------------------------------------------
// Kernel 4: out = F*x + fb + x, pipelined.
// ---------------------------------------------------------------------------
__global__ void __launch_bounds__(256, 2)
out_tc(const float* __restrict__ x, float* __restrict__ dout)
{
    __shared__ uint32_t As[2][8][LDS_];
    __shared__ uint32_t Bs[2][8][LDS_];
    const int n0 = blockIdx.x << 7;
    const int b  = blockIdx.y;
    const float* xb = x + (size_t)b * C * N;

    const int tid = threadIdx.x, lane = tid & 31, warp = tid >> 5;
    const int g = lane >> 2, tig = lane & 3;
    const int warpM = warp & 1, warpN = warp >> 1;
    const int mrow = warpM * 64, ncol = warpN * 32;

    const int am = tid >> 1;
    const float* aptr = g_F + (size_t)b * C * C + (size_t)am * C + ((tid & 1) << 2);
    const float* bptr = xb + (size_t)(tid >> 5) * N + n0 + ((tid & 31) << 2);

    float4 ra = *(const float4*)aptr;
    float4 rb = *(const float4*)bptr;
    stsT(As[0], ra, tid); stsD(Bs[0], rb, tid);
    __syncthreads();

    float acc[4][4][4] = {};
#pragma unroll 1
    for (int s = 0; s < 16; s++) {
        const int cur = s & 1;
        if (s < 15) {
            ra = *(const float4*)(aptr + (s + 1) * 8);
            rb = *(const float4*)(bptr + (size_t)(s + 1) * 8 * N);
        }
        compute_slab8(As[cur], Bs[cur], acc, mrow, ncol, g, tig);
        if (s < 15) { stsT(As[cur ^ 1], ra, tid); stsD(Bs[cur ^ 1], rb, tid); __syncthreads(); }
    }

#pragma unroll
    for (int mf = 0; mf < 4; mf++) {
        const int o = mrow + mf * 16 + g;
        const float fb0 = g_fb[(size_t)b * C + o];
        const float fb1 = g_fb[(size_t)b * C + o + 8];
#pragma unroll
        for (int nf = 0; nf < 4; nf++) {
            const int col = n0 + ncol + nf * 8 + 2 * tig;
            float2 r0 = *(const float2*)(xb + (size_t)o * N + col);
            float2 r1 = *(const float2*)(xb + (size_t)(o + 8) * N + col);
            *(float2*)(dout + ((size_t)b * C + o) * N + col) =
                make_float2(acc[mf][nf][0] + fb0 + r0.x, acc[mf][nf][1] + fb0 + r0.y);
            *(float2*)(dout + ((size_t)b * C + o + 8) * N + col) =
                make_float2(acc[mf][nf][2] + fb1 + r1.x, acc[mf][nf][3] + fb1 + r1.y);
        }
    }
}

// ---------------------------------------------------------------------------
extern "C" void kernel_launch(void* const* d_in, const int* in_sizes, int n_in,
                              void* d_out, int out_size)
{
    const float* x    = (const float*)d_in[0];
    const float* prev = (const float*)d_in[1];
    const float* Wq   = (const float*)d_in[2];
    const float* bq   = (const float*)d_in[3];
    const float* Wk   = (const float*)d_in[4];
    const float* bk   = (const float*)d_in[5];
    const float* Wv   = (const float*)d_in[6];
    const float* bv   = (const float*)d_in[7];
    const float* Wg   = (const float*)d_in[8];
    const float* bg   = (const float*)d_in[9];
    const float* Wp   = (const float*)d_in[10];
    const float* bp   = (const float*)d_in[11];
    float* out = (float*)d_out;

    proj_tc<<<dim3(4, NTILES, BATCH), 256>>>(x, Wk, bk, Wv, bv, Wg, bg);
    know_tc<<<dim3(SPLITK, BATCH), 256>>>();
    tail_tc<<<BATCH, 256>>>(prev, Wp, Wq, bq, bp, out);
    out_tc<<<dim3(NTILES, BATCH), 256>>>(x, out);
}